// round 7
// baseline (speedup 1.0000x reference)
#include <cuda_runtime.h>

// Problem constants
#define T_STEPS 256
#define BATCH   128
#define HID     1024
#define LAT     128
#define PIECE   128

#define NBLK 128            // one CTA per 8 hidden units; co-resident (<=148 SMs)
#define NTHR 512            // 16 warps -> 4 per SMSP; two 256-thread k-halves
#define KC   32             // k-chunk of h streamed through smem
#define NCH_HALF 16         // chunks per k-half (512 k each)

typedef unsigned long long ull;

// Persistent state (device globals)
__device__ float    g_h[2][HID * BATCH];  // h double buffer, layout [k][b]
__device__ unsigned g_bar;                // monotonic grid-barrier counter

// ---------------- helpers ----------------
__device__ __forceinline__ void cp_async16(void* sdst, const void* gsrc) {
    unsigned s = (unsigned)__cvta_generic_to_shared(sdst);
    asm volatile("cp.async.cg.shared.global [%0], [%1], 16;\n" :: "r"(s), "l"(gsrc));
}
__device__ __forceinline__ void cp_commit() { asm volatile("cp.async.commit_group;\n"); }
__device__ __forceinline__ void cp_wait0()  { asm volatile("cp.async.wait_group 0;\n"); }

__device__ __forceinline__ ull pack2(float lo, float hi) {
    ull r; asm("mov.b64 %0, {%1, %2};" : "=l"(r) : "f"(lo), "f"(hi)); return r;
}
__device__ __forceinline__ void unpack2(ull v, float& lo, float& hi) {
    asm("mov.b64 {%0, %1}, %2;" : "=f"(lo), "=f"(hi) : "l"(v));
}
__device__ __forceinline__ void ffma2(ull& d, ull a, ull b) {
    asm("fma.rn.f32x2 %0, %1, %2, %0;" : "+l"(d) : "l"(a), "l"(b));
}
__device__ __forceinline__ float sigf(float x) { return 1.0f / (1.0f + __expf(-x)); }

// Named barrier over one 256-thread k-half (warp-aligned halves; IDs 1,2)
__device__ __forceinline__ void bar_half(int kh) {
    asm volatile("bar.sync %0, 256;" :: "r"(1 + kh) : "memory");
}

// Grid barrier: 128 CTAs co-resident (1 CTA/SM). Every thread fences its own
// stores before arrival. Monotonic counter => valid across graph replays.
__device__ __forceinline__ void grid_bar() {
    __threadfence();
    __syncthreads();
    if (threadIdx.x == 0) {
        unsigned my = atomicAdd(&g_bar, 1u);
        unsigned target = my - (my % NBLK) + NBLK;
        while (*(volatile unsigned*)&g_bar < target) { __nanosleep(40); }
        __threadfence();
    }
    __syncthreads();
}

// ---------------- persistent kernel ----------------
// CTA blk owns hidden units u = blk*8..blk*8+7 (4 gates each, 32 gate cols) for
// all 128 batch rows, plus FC output column p = blk.
// Thread: kh = tid>>8 (k-half), th = tid&255, tx = th&7 (unit), tyq = th>>3
// (0..31 -> batch rows tyq*4..tyq*4+3).
// GEMM tile per thread: 4 batch rows x 4 gate cols over its 512-k half
// (acc lanes = batch rows 2p, 2p+1). Halves exchange one batch-pair per thread.
extern "C" __global__ void __launch_bounds__(NTHR, 1)
lstm_persistent_kernel(const float* __restrict__ z,
                       const float* __restrict__ w_ih,
                       const float* __restrict__ w_hh,
                       const float* __restrict__ b_ih,
                       const float* __restrict__ b_hh,
                       const float* __restrict__ W_fc,
                       const float* __restrict__ b_fc,
                       float* __restrict__ out)
{
    extern __shared__ float smem[];
    float* Wsm    = smem;                    // [HID][32] w_hh slice, k-major (128 KB)
    float* Hst    = Wsm + HID * 32;          // 4 bufs of KC*BATCH (kh,buf)    (64 KB)
    float* wfcs   = Hst + 4 * KC * BATCH;    // [HID] W_fc row blk              (4 KB)
    float* bsum   = wfcs + HID;              // [32] b_ih + b_hh slice
    float* fcpart = bsum + 32;               // [4][128] FC partials
    float* poolf  = fcpart + 512;            // 17.4 KB pool: exch / Xg alias
    ull*   exch   = (ull*)poolf;             // [(kh*32+tyq)*34 + tx*4 + j]
    float* Xg     = poolf;                   // [32][128] step-0 gates (alias)

    const int tid = threadIdx.x;
    const int blk = blockIdx.x;
    const int kh  = tid >> 8;     // k-half
    const int th  = tid & 255;    // id within half
    const int tx  = th & 7;       // unit
    const int tyq = th >> 3;      // batch quad (4 rows)

    // ---------- prologue ----------
    for (int col = 0; col < 32; ++col) {
        int u = col >> 2, g = col & 3;
        const float* src = w_hh + (size_t)(g * HID + blk * 8 + u) * HID;
        for (int k = tid; k < HID; k += NTHR)
            Wsm[k * 32 + col] = src[k];
    }
    if (tid < 32) {
        int u = tid >> 2, g = tid & 3;
        bsum[tid] = b_ih[g * HID + blk * 8 + u] + b_hh[g * HID + blk * 8 + u];
    }
    for (int k = tid; k < HID; k += NTHR) wfcs[k] = W_fc[(size_t)blk * HID + k];
    const float bfc = b_fc[blk];

    // Step-0 input gates: Xg[col][b] = z[b,:] . w_ih[row(col),:]  (8 dots/thread)
    for (int i = 0; i < 8; ++i) {
        int d = tid * 8 + i;          // 0..4095
        int col = d >> 7, b = d & 127;
        int u = col >> 2, g = col & 3;
        const float* wi = w_ih + (size_t)(g * HID + blk * 8 + u) * LAT;
        const float* zb = z + (size_t)b * LAT;
        float s = 0.f;
        #pragma unroll 4
        for (int l = 0; l < LAT; ++l) s += zb[l] * wi[l];
        Xg[col * BATCH + b] = s;
    }
    __syncthreads();

    // kept batch pair p = kh -> rows b0 = tyq*4 + 2*kh, b0+1
    const int b0 = tyq * 4 + 2 * kh;
    float cst[2] = {0.f, 0.f};

    const int fcsub = th >> 7;        // FC k-sub within chunk
    const int fcb   = th & 127;       // FC batch row

    for (int t = 0; t <= T_STEPS; ++t) {
        ull acc[2][4];   // [batch pair p][gate j], lanes = rows (2p, 2p+1)
        float yacc = 0.f;

        if (t >= 1) {
            #pragma unroll
            for (int p = 0; p < 2; ++p)
                #pragma unroll
                for (int j = 0; j < 4; ++j) acc[p][j] = 0;

            const float* hsrc = g_h[t & 1];       // h_{t-1}, [k][b]
            const size_t hoff = (size_t)kh * 512 * BATCH;

            // prefetch chunk 0 of this half (coalesced 16B)
            {
                float* dst = Hst + (kh * 2) * (KC * BATCH);
                const float* src = hsrc + hoff;
                #pragma unroll
                for (int r = 0; r < 4; ++r)
                    cp_async16(dst + (size_t)(th + 256 * r) * 4,
                               src + (size_t)(th + 256 * r) * 4);
                cp_commit();
            }

            for (int ck = 0; ck < NCH_HALF; ++ck) {
                cp_wait0();
                bar_half(kh);

                if (ck + 1 < NCH_HALF) {
                    float* dst = Hst + (kh * 2 + ((ck + 1) & 1)) * (KC * BATCH);
                    const float* src = hsrc + hoff + (size_t)(ck + 1) * KC * BATCH;
                    #pragma unroll
                    for (int r = 0; r < 4; ++r)
                        cp_async16(dst + (size_t)(th + 256 * r) * 4,
                                   src + (size_t)(th + 256 * r) * 4);
                    cp_commit();
                }

                const float* hb = Hst + (kh * 2 + (ck & 1)) * (KC * BATCH);
                const float* wb = Wsm + (size_t)(kh * 512 + ck * KC) * 32;

                // GEMM: per k: 2x LDS.128 + 4 pack MOV + 8 FFMA2
                #pragma unroll 8
                for (int k = 0; k < KC; ++k) {
                    float4 w4 = *(const float4*)(wb + k * 32 + tx * 4);
                    ull w2[4] = { pack2(w4.x, w4.x), pack2(w4.y, w4.y),
                                  pack2(w4.z, w4.z), pack2(w4.w, w4.w) };
                    ulonglong2 hv = *(const ulonglong2*)(hb + k * BATCH + tyq * 4);
                    #pragma unroll
                    for (int j = 0; j < 4; ++j) {
                        ffma2(acc[0][j], hv.x, w2[j]);
                        ffma2(acc[1][j], hv.y, w2[j]);
                    }
                }

                // FC partial for y_{t-1}: batch row fcb, k-sub fcsub of chunk
                {
                    const float* hfc = hb + fcsub * 16 * BATCH + fcb;
                    const float* wf  = wfcs + kh * 512 + ck * KC + fcsub * 16;
                    #pragma unroll
                    for (int k = 0; k < 16; ++k)
                        yacc += hfc[k * BATCH] * wf[k];
                }
            }

            fcpart[(kh * 2 + fcsub) * 128 + fcb] = yacc;

            // donate pair pd = 1-kh to the sibling thread in the other half
            {
                ull* e = exch + (size_t)(kh * 32 + tyq) * 34 + tx * 4;
                ulonglong2* ev = (ulonglong2*)e;
                ev[0] = make_ulonglong2(acc[1 - kh][0], acc[1 - kh][1]);
                ev[1] = make_ulonglong2(acc[1 - kh][2], acc[1 - kh][3]);
            }
        }

        __syncthreads();   // fcpart + exch visible CTA-wide

        if (t >= 1 && tid < 128)
            out[(size_t)tid * (T_STEPS * PIECE) + (size_t)(t - 1) * PIECE + blk]
                = fcpart[tid] + fcpart[128 + tid] + fcpart[256 + tid]
                + fcpart[384 + tid] + bfc;

        if (t < T_STEPS) {
            // epilogue for kept rows b0, b0+1, unit tx
            float glo[4], ghi[4];
            if (t == 0) {
                #pragma unroll
                for (int j = 0; j < 4; ++j) {
                    glo[j] = Xg[(tx * 4 + j) * BATCH + b0]     + bsum[tx * 4 + j];
                    ghi[j] = Xg[(tx * 4 + j) * BATCH + b0 + 1] + bsum[tx * 4 + j];
                }
            } else {
                const ull* e = exch + (size_t)((1 - kh) * 32 + tyq) * 34 + tx * 4;
                #pragma unroll
                for (int j = 0; j < 4; ++j) {
                    float al, ah, bl, bh;
                    unpack2(acc[kh][j], al, ah);
                    unpack2(e[j], bl, bh);
                    glo[j] = al + bl + bsum[tx * 4 + j];
                    ghi[j] = ah + bh + bsum[tx * 4 + j];
                }
            }
            float h0, h1;
            {
                float i_ = sigf(glo[0]), f_ = sigf(glo[1]);
                float g_ = tanhf(glo[2]), o_ = sigf(glo[3]);
                float c = f_ * cst[0] + i_ * g_;
                cst[0] = c;
                h0 = o_ * tanhf(c);
            }
            {
                float i_ = sigf(ghi[0]), f_ = sigf(ghi[1]);
                float g_ = tanhf(ghi[2]), o_ = sigf(ghi[3]);
                float c = f_ * cst[1] + i_ * g_;
                cst[1] = c;
                h1 = o_ * tanhf(c);
            }
            // write h_t[row = blk*8+tx][b0..b0+1]
            float2* hd = (float2*)(g_h[(t + 1) & 1]
                         + (size_t)(blk * 8 + tx) * BATCH + b0);
            *hd = make_float2(h0, h1);

            grid_bar();   // h_t visible to all CTAs before step t+1
        }
    }
}

// ---------------- launch ----------------
extern "C" void kernel_launch(void* const* d_in, const int* in_sizes, int n_in,
                              void* d_out, int out_size)
{
    // metadata order: current_batch_size, z, w_ih, w_hh, b_ih, b_hh, W_fc, b_fc
    int off = (n_in >= 8) ? 1 : 0;
    const float* z    = (const float*)d_in[off + 0];
    const float* w_ih = (const float*)d_in[off + 1];
    const float* w_hh = (const float*)d_in[off + 2];
    const float* b_ih = (const float*)d_in[off + 3];
    const float* b_hh = (const float*)d_in[off + 4];
    const float* W_fc = (const float*)d_in[off + 5];
    const float* b_fc = (const float*)d_in[off + 6];

    // pool: exch = 2*32*34 ull = 2176 ull = 4352 floats (Xg aliases first 4096)
    const int smem_bytes = (HID * 32 + 4 * KC * BATCH + HID + 32 + 512 + 4352)
                           * (int)sizeof(float);
    cudaFuncSetAttribute(lstm_persistent_kernel,
                         cudaFuncAttributeMaxDynamicSharedMemorySize, smem_bytes);

    lstm_persistent_kernel<<<NBLK, NTHR, smem_bytes>>>(
        z, w_ih, w_hh, b_ih, b_hh, W_fc, b_fc, (float*)d_out);
}

// round 10
// speedup vs baseline: 1.3618x; 1.3618x over previous
#include <cuda_runtime.h>
#include <cuda_bf16.h>
#include <cstdint>

// Problem constants
#define T_STEPS 256
#define BATCH   128
#define HID     1024
#define LAT     128
#define PIECE   128

#define NBLK 128            // one CTA per 8 hidden units (32 gate cols); 1 CTA/SM
#define NTHR 256            // 8 warps: warp w owns batch rows w*16..w*16+15
#define KCH  32             // k per streamed chunk
#define NCHUNK 32

// B: 40 rows (32 gates + 1 FC + 7 zero pad) x 1024 k, row pad +8 elems
#define BSTR 1032                      // elems per B row (+16B pad: conflict-free ldmatrix)
#define ASTR 40                        // elems per A row (32 k + 8 pad -> 80B stride)
#define OFF_BHI 0                      // 40*1032*2 = 82560 B
#define OFF_BLO (40 * BSTR * 2)        // 82560
#define OFF_A   (2 * 40 * BSTR * 2)    // 165120 ; 4 bufs: [stage][hi,lo]
#define A_BUF   (BATCH * ASTR * 2)     // 10240 B per component buffer
#define OFF_MISC (OFF_A + 4 * A_BUF)   // 206080 ; bsum[32] floats
#define SMEM_BYTES (OFF_MISC + 256)

typedef unsigned long long ull;

// Persistent state
__device__ __nv_bfloat16 g_hsp[2][2][BATCH * HID];  // [time buf][hi/lo][b][k]
__device__ unsigned g_bar;                          // monotonic grid barrier

// ---------------- helpers ----------------
__device__ __forceinline__ uint32_t smem_u32(const void* p) {
    uint32_t a;
    asm("{ .reg .u64 t; cvta.to.shared.u64 t, %1; cvt.u32.u64 %0, t; }"
        : "=r"(a) : "l"(p));
    return a;
}
__device__ __forceinline__ void cp_async16(uint32_t sdst, const void* gsrc) {
    asm volatile("cp.async.cg.shared.global [%0], [%1], 16;\n" :: "r"(sdst), "l"(gsrc));
}
__device__ __forceinline__ void cp_commit() { asm volatile("cp.async.commit_group;\n"); }
__device__ __forceinline__ void cp_wait0()  { asm volatile("cp.async.wait_group 0;\n"); }

__device__ __forceinline__ void ldsm4(uint32_t* r, uint32_t addr) {
    asm volatile("ldmatrix.sync.aligned.m8n8.x4.shared.b16 {%0,%1,%2,%3}, [%4];"
                 : "=r"(r[0]), "=r"(r[1]), "=r"(r[2]), "=r"(r[3]) : "r"(addr));
}
__device__ __forceinline__ void ldsm2(uint32_t* r, uint32_t addr) {
    asm volatile("ldmatrix.sync.aligned.m8n8.x2.shared.b16 {%0,%1}, [%2];"
                 : "=r"(r[0]), "=r"(r[1]) : "r"(addr));
}
// mma.sync m16n8k16 row.col f32.bf16.bf16.f32 (sm_80+, valid on plain sm_103)
__device__ __forceinline__ void mma16816(float* d, const uint32_t* a, const uint32_t* b) {
    asm volatile(
        "mma.sync.aligned.m16n8k16.row.col.f32.bf16.bf16.f32 "
        "{%0,%1,%2,%3}, {%4,%5,%6,%7}, {%8,%9}, {%0,%1,%2,%3};"
        : "+f"(d[0]), "+f"(d[1]), "+f"(d[2]), "+f"(d[3])
        : "r"(a[0]), "r"(a[1]), "r"(a[2]), "r"(a[3]), "r"(b[0]), "r"(b[1]));
}
__device__ __forceinline__ float sigf(float x) { return 1.0f / (1.0f + __expf(-x)); }

// Grid barrier (128 co-resident CTAs; monotonic counter, graph-replay safe)
__device__ __forceinline__ void grid_bar() {
    __threadfence();
    __syncthreads();
    if (threadIdx.x == 0) {
        unsigned my = atomicAdd(&g_bar, 1u);
        unsigned target = my - (my % NBLK) + NBLK;
        while (*(volatile unsigned*)&g_bar < target) { __nanosleep(40); }
        __threadfence();
    }
    __syncthreads();
}

// ---------------- persistent mma.sync kernel ----------------
// Per step, per CTA: D[128 x 40] = h_split[128 x 1024] . B^T, B rows:
//   n = u*4+g (u=0..7 local unit, g: 0=i,1=f,2=g,3=o) -> w_hh[g*HID+blk*8+u][:]
//   n = 32 -> W_fc[blk][:]   (FC folded into the GEMM)
// Split bf16: D = Ahi.Bhi + Ahi.Blo + Alo.Bhi  (fp32 accum)
extern "C" __global__ void __launch_bounds__(NTHR, 1)
lstm_mma_kernel(const float* __restrict__ z,
                const float* __restrict__ w_ih,
                const float* __restrict__ w_hh,
                const float* __restrict__ b_ih,
                const float* __restrict__ b_hh,
                const float* __restrict__ W_fc,
                const float* __restrict__ b_fc,
                float* __restrict__ out)
{
    extern __shared__ char smem[];
    const uint32_t sbase = smem_u32(smem);
    float* bsum = (float*)(smem + OFF_MISC);         // [32] gate biases
    float* Xg   = (float*)(smem + OFF_A);            // [32][128] f32, t=0 only (alias)

    const int tid  = threadIdx.x;
    const int blk  = blockIdx.x;
    const int wid  = tid >> 5;
    const int lane = tid & 31;

    // ---------- prologue: build B (split bf16) ----------
    {   // zero whole B region (covers pad rows/cols)
        uint4 zz = make_uint4(0, 0, 0, 0);
        uint4* bb = (uint4*)smem;
        for (int i = tid; i < (2 * 40 * BSTR * 2) / 16; i += NTHR) bb[i] = zz;
    }
    __syncthreads();
    for (int e = tid; e < 32 * HID; e += NTHR) {
        int n = e >> 10, k = e & 1023;
        int u = n >> 2, g = n & 3;
        float x = w_hh[(size_t)(g * HID + blk * 8 + u) * HID + k];
        __nv_bfloat16 hi = __float2bfloat16(x);
        __nv_bfloat16 lo = __float2bfloat16(x - __bfloat162float(hi));
        *(__nv_bfloat16*)(smem + OFF_BHI + ((size_t)n * BSTR + k) * 2) = hi;
        *(__nv_bfloat16*)(smem + OFF_BLO + ((size_t)n * BSTR + k) * 2) = lo;
    }
    for (int k = tid; k < HID; k += NTHR) {          // FC row n = 32
        float x = W_fc[(size_t)blk * HID + k];
        __nv_bfloat16 hi = __float2bfloat16(x);
        __nv_bfloat16 lo = __float2bfloat16(x - __bfloat162float(hi));
        *(__nv_bfloat16*)(smem + OFF_BHI + ((size_t)32 * BSTR + k) * 2) = hi;
        *(__nv_bfloat16*)(smem + OFF_BLO + ((size_t)32 * BSTR + k) * 2) = lo;
    }
    if (tid < 32) {
        int u = tid >> 2, g = tid & 3;
        bsum[tid] = b_ih[g * HID + blk * 8 + u] + b_hh[g * HID + blk * 8 + u];
    }
    const float bfc = b_fc[blk];

    // Step-0 input gates: Xg[n][b] = z[b,:] . w_ih[row(n),:]
    for (int d = tid; d < 32 * BATCH; d += NTHR) {
        int n = d >> 7, b = d & 127;
        int u = n >> 2, g = n & 3;
        const float* wi = w_ih + (size_t)(g * HID + blk * 8 + u) * LAT;
        const float* zb = z + (size_t)b * LAT;
        float s = 0.f;
        #pragma unroll 4
        for (int l = 0; l < LAT; ++l) s += zb[l] * wi[l];
        Xg[n * BATCH + b] = s;
    }
    __syncthreads();

    // ldmatrix per-lane address offsets
    // A (x4): m0 rows0-7/k0-7, m1 rows8-15/k0-7, m2 rows0-7/k8-15, m3 rows8-15/k8-15
    const uint32_t aoff = (uint32_t)((wid * 16 + (lane & 15)) * (ASTR * 2)
                                     + (lane >> 4) * 16);
    // B (x2): lanes 0-7 rows n0..7/k0-7, lanes 8-15 rows n0..7/k8-15
    const uint32_t bofft = (uint32_t)((lane & 7) * (BSTR * 2) + ((lane >> 3) & 1) * 16);

    // epilogue identity: pair (lane, lane^1); parity = lane&1 selects row r or r+8
    const int par = lane & 1;
    const int r_e = wid * 16 + (lane >> 2) + 8 * par;
    const int uo  = (lane >> 1) & 1;          // unit offset within n8 tile

    float cst[4] = {0.f, 0.f, 0.f, 0.f};      // c-state: units 2j+uo, row r_e

    for (int t = 0; t <= T_STEPS; ++t) {
        float d[5][4];
        #pragma unroll
        for (int j = 0; j < 5; ++j)
            #pragma unroll
            for (int q = 0; q < 4; ++q) d[j][q] = 0.f;

        if (t >= 1) {
            const __nv_bfloat16* hhi = g_hsp[t & 1][0];
            const __nv_bfloat16* hlo = g_hsp[t & 1][1];

            // prefetch chunk 0 -> stage 0: hi @ +0, lo @ +A_BUF   (FIXED)
            {
                #pragma unroll
                for (int i = 0; i < 2; ++i) {
                    int s = tid * 2 + i;  int b = s >> 2, seg = s & 3;
                    uint32_t dst = sbase + OFF_A + b * (ASTR * 2) + seg * 16;
                    cp_async16(dst,         hhi + (size_t)b * HID + seg * 8);
                    cp_async16(dst + A_BUF, hlo + (size_t)b * HID + seg * 8);
                }
                cp_commit();
            }

            for (int c = 0; c < NCHUNK; ++c) {
                cp_wait0();
                __syncthreads();          // chunk c landed; stage c&1 readable

                if (c + 1 < NCHUNK) {     // prefetch c+1 into stage (c+1)&1
                    uint32_t st = ((c + 1) & 1) * (2 * A_BUF);
                    #pragma unroll
                    for (int i = 0; i < 2; ++i) {
                        int s = tid * 2 + i;  int b = s >> 2, seg = s & 3;
                        uint32_t dst = sbase + OFF_A + st + b * (ASTR * 2) + seg * 16;
                        const size_t go = (size_t)b * HID + (c + 1) * KCH + seg * 8;
                        cp_async16(dst,         hhi + go);    // hi @ +0
                        cp_async16(dst + A_BUF, hlo + go);    // lo @ +A_BUF (FIXED)
                    }
                    cp_commit();
                }

                const uint32_t aHi = sbase + OFF_A + (c & 1) * (2 * A_BUF) + aoff;
                const uint32_t aLo = aHi + A_BUF;             // (FIXED: was +2*A_BUF)
                const uint32_t bB  = sbase + bofft + (uint32_t)c * (KCH * 2);

                #pragma unroll
                for (int kk = 0; kk < 2; ++kk) {
                    uint32_t ahi[4], alo[4];
                    ldsm4(ahi, aHi + kk * 32);
                    ldsm4(alo, aLo + kk * 32);
                    #pragma unroll
                    for (int j = 0; j < 5; ++j) {
                        uint32_t bhi[2], blo[2];
                        uint32_t brow = bB + (uint32_t)(j * 8) * (BSTR * 2) + kk * 32;
                        ldsm2(bhi, brow + OFF_BHI);
                        ldsm2(blo, brow + OFF_BLO);
                        mma16816(d[j], ahi, bhi);
                        mma16816(d[j], ahi, blo);
                        mma16816(d[j], alo, bhi);
                    }
                }
            }
        }

        // ---------- epilogue ----------
        // y (D col 32, tile 4): lane&3==0 holds row r (d[4][0]); its partner
        // (lane&3==1) receives row r+8 via shfl of d[4][2].
        if (t >= 1) {
            float ysh = __shfl_xor_sync(0xffffffffu, d[4][2], 1);
            int l3 = lane & 3;
            if (l3 == 0)
                out[(size_t)r_e * (T_STEPS * PIECE) + (size_t)(t - 1) * PIECE + blk]
                    = d[4][0] + bfc;
            else if (l3 == 1)
                out[(size_t)r_e * (T_STEPS * PIECE) + (size_t)(t - 1) * PIECE + blk]
                    = ysh + bfc;
        }

        if (t < T_STEPS) {
            __nv_bfloat16 hh[4], hl[4];
            #pragma unroll
            for (int j = 0; j < 4; ++j) {
                int u = 2 * j + uo;
                float gv[4];
                if (t == 0) {
                    #pragma unroll
                    for (int g = 0; g < 4; ++g)
                        gv[g] = Xg[(u * 4 + g) * BATCH + r_e] + bsum[u * 4 + g];
                } else {
                    float x0 = __shfl_xor_sync(0xffffffffu, d[j][0], 1);
                    float x1 = __shfl_xor_sync(0xffffffffu, d[j][1], 1);
                    float x2 = __shfl_xor_sync(0xffffffffu, d[j][2], 1);
                    float x3 = __shfl_xor_sync(0xffffffffu, d[j][3], 1);
                    if (par == 0) {         // row r: own = gates 0,1 ; partner = 2,3
                        gv[0] = d[j][0]; gv[1] = d[j][1]; gv[2] = x0; gv[3] = x1;
                    } else {                // row r+8: partner = gates 0,1 ; own = 2,3
                        gv[0] = x2; gv[1] = x3; gv[2] = d[j][2]; gv[3] = d[j][3];
                    }
                    #pragma unroll
                    for (int g = 0; g < 4; ++g) gv[g] += bsum[u * 4 + g];
                }
                float i_ = sigf(gv[0]), f_ = sigf(gv[1]);
                float g_ = tanhf(gv[2]), o_ = sigf(gv[3]);
                float cc = f_ * cst[j] + i_ * g_;
                cst[j] = cc;
                float hv = o_ * tanhf(cc);
                __nv_bfloat16 hi = __float2bfloat16(hv);
                hh[j] = hi;
                hl[j] = __float2bfloat16(hv - __bfloat162float(hi));
            }
            // store h_t split: k = blk*8 + 2j + uo, row r_e
            __nv_bfloat16* dh = g_hsp[(t + 1) & 1][0] + (size_t)r_e * HID + blk * 8 + uo;
            __nv_bfloat16* dl = g_hsp[(t + 1) & 1][1] + (size_t)r_e * HID + blk * 8 + uo;
            #pragma unroll
            for (int j = 0; j < 4; ++j) { dh[2 * j] = hh[j]; dl[2 * j] = hl[j]; }

            grid_bar();     // h_t visible to all CTAs before step t+1
        }
    }
}

// ---------------- launch ----------------
extern "C" void kernel_launch(void* const* d_in, const int* in_sizes, int n_in,
                              void* d_out, int out_size)
{
    // metadata order: current_batch_size, z, w_ih, w_hh, b_ih, b_hh, W_fc, b_fc
    int off = (n_in >= 8) ? 1 : 0;
    const float* z    = (const float*)d_in[off + 0];
    const float* w_ih = (const float*)d_in[off + 1];
    const float* w_hh = (const float*)d_in[off + 2];
    const float* b_ih = (const float*)d_in[off + 3];
    const float* b_hh = (const float*)d_in[off + 4];
    const float* W_fc = (const float*)d_in[off + 5];
    const float* b_fc = (const float*)d_in[off + 6];

    cudaFuncSetAttribute(lstm_mma_kernel,
                         cudaFuncAttributeMaxDynamicSharedMemorySize, SMEM_BYTES);

    lstm_mma_kernel<<<NBLK, NTHR, SMEM_BYTES>>>(
        z, w_ih, w_hh, b_ih, b_hh, W_fc, b_fc, (float*)d_out);
}

// round 11
// speedup vs baseline: 1.8754x; 1.3771x over previous
#include <cuda_runtime.h>
#include <cuda_bf16.h>
#include <cstdint>

// Problem constants
#define T_STEPS 256
#define BATCH   128
#define HID     1024
#define LAT     128
#define PIECE   128

#define NBLK 128            // one CTA per 8 hidden units (32 gate cols); 1 CTA/SM
#define NTHR 256            // 8 warps: warp w owns batch rows w*16..w*16+15
#define KCH  32             // k per streamed chunk
#define NCHUNK 32

// B: 40 rows (32 gates + 1 FC + 7 zero pad) x 1024 k, row pad +8 elems
#define BSTR 1032                      // elems per B row (+16B pad)
#define ASTR 40                        // elems per A row (32 k + 8 pad -> 80B stride)
#define OFF_BHI 0                      // 40*1032*2 = 82560 B
#define OFF_BLO (40 * BSTR * 2)        // 82560
#define OFF_A   (2 * 40 * BSTR * 2)    // 165120 ; per-warp 3-stage staging
#define A_COMP  (16 * ASTR * 2)        // 1280 B: one component (16 rows x 80B)
#define A_WSTG  (2 * A_COMP)           // 2560 B: one stage (hi+lo)
#define A_WREG  (3 * A_WSTG)           // 7680 B: per-warp region (3 stages)
#define OFF_MISC (OFF_A + 8 * A_WREG)  // 226560 ; bsum[32] floats
#define SMEM_BYTES (OFF_MISC + 256)    // 226816

typedef unsigned long long ull;

// Persistent state
__device__ __nv_bfloat16 g_hsp[2][2][BATCH * HID];  // [time buf][hi/lo][b][k]
__device__ unsigned g_bar;                          // monotonic grid barrier

// ---------------- helpers ----------------
__device__ __forceinline__ uint32_t smem_u32(const void* p) {
    uint32_t a;
    asm("{ .reg .u64 t; cvta.to.shared.u64 t, %1; cvt.u32.u64 %0, t; }"
        : "=r"(a) : "l"(p));
    return a;
}
__device__ __forceinline__ void cp_async16(uint32_t sdst, const void* gsrc) {
    asm volatile("cp.async.cg.shared.global [%0], [%1], 16;\n" :: "r"(sdst), "l"(gsrc));
}
__device__ __forceinline__ void cp_commit() { asm volatile("cp.async.commit_group;\n"); }
__device__ __forceinline__ void cp_wait0()  { asm volatile("cp.async.wait_group 0;\n"); }
__device__ __forceinline__ void cp_wait1()  { asm volatile("cp.async.wait_group 1;\n"); }
__device__ __forceinline__ void cp_wait2()  { asm volatile("cp.async.wait_group 2;\n"); }

__device__ __forceinline__ void ldsm4(uint32_t* r, uint32_t addr) {
    asm volatile("ldmatrix.sync.aligned.m8n8.x4.shared.b16 {%0,%1,%2,%3}, [%4];"
                 : "=r"(r[0]), "=r"(r[1]), "=r"(r[2]), "=r"(r[3]) : "r"(addr));
}
__device__ __forceinline__ void ldsm2(uint32_t* r, uint32_t addr) {
    asm volatile("ldmatrix.sync.aligned.m8n8.x2.shared.b16 {%0,%1}, [%2];"
                 : "=r"(r[0]), "=r"(r[1]) : "r"(addr));
}
// mma.sync m16n8k16 row.col f32.bf16.bf16.f32
__device__ __forceinline__ void mma16816(float* d, const uint32_t* a, const uint32_t* b) {
    asm volatile(
        "mma.sync.aligned.m16n8k16.row.col.f32.bf16.bf16.f32 "
        "{%0,%1,%2,%3}, {%4,%5,%6,%7}, {%8,%9}, {%0,%1,%2,%3};"
        : "+f"(d[0]), "+f"(d[1]), "+f"(d[2]), "+f"(d[3])
        : "r"(a[0]), "r"(a[1]), "r"(a[2]), "r"(a[3]), "r"(b[0]), "r"(b[1]));
}
__device__ __forceinline__ float sigf(float x) { return 1.0f / (1.0f + __expf(-x)); }

// Grid barrier (128 co-resident CTAs; monotonic counter, graph-replay safe)
__device__ __forceinline__ void grid_bar() {
    __threadfence();
    __syncthreads();
    if (threadIdx.x == 0) {
        unsigned my = atomicAdd(&g_bar, 1u);
        unsigned target = my - (my % NBLK) + NBLK;
        while (*(volatile unsigned*)&g_bar < target) { __nanosleep(40); }
        __threadfence();
    }
    __syncthreads();
}

// ---------------- persistent mma.sync kernel ----------------
// Per step, per CTA: D[128 x 40] = h_split[128 x 1024] . B^T, B rows:
//   n = u*4+g (u local unit, g: 0=i,1=f,2=g,3=o) -> w_hh[g*HID+blk*8+u][:]
//   n = 32 -> W_fc[blk][:]   (FC folded into the GEMM)
// Split bf16: D = Ahi.Bhi + Ahi.Blo + Alo.Bhi  (fp32 accum)
// Warp-private A staging, 3 stages, 2 cp.async groups in flight, no block
// syncs inside the chunk loop.
extern "C" __global__ void __launch_bounds__(NTHR, 1)
lstm_mma_kernel(const float* __restrict__ z,
                const float* __restrict__ w_ih,
                const float* __restrict__ w_hh,
                const float* __restrict__ b_ih,
                const float* __restrict__ b_hh,
                const float* __restrict__ W_fc,
                const float* __restrict__ b_fc,
                float* __restrict__ out)
{
    extern __shared__ char smem[];
    const uint32_t sbase = smem_u32(smem);
    float* bsum = (float*)(smem + OFF_MISC);         // [32] gate biases
    float* Xg   = (float*)(smem + OFF_A);            // [32][128] f32, t=0 only (alias)

    const int tid  = threadIdx.x;
    const int blk  = blockIdx.x;
    const int wid  = tid >> 5;
    const int lane = tid & 31;

    // ---------- prologue: build B (split bf16) ----------
    {   // zero whole B region (covers pad rows/cols)
        uint4 zz = make_uint4(0, 0, 0, 0);
        uint4* bb = (uint4*)smem;
        for (int i = tid; i < (2 * 40 * BSTR * 2) / 16; i += NTHR) bb[i] = zz;
    }
    __syncthreads();
    for (int e = tid; e < 32 * HID; e += NTHR) {
        int n = e >> 10, k = e & 1023;
        int u = n >> 2, g = n & 3;
        float x = w_hh[(size_t)(g * HID + blk * 8 + u) * HID + k];
        __nv_bfloat16 hi = __float2bfloat16(x);
        __nv_bfloat16 lo = __float2bfloat16(x - __bfloat162float(hi));
        *(__nv_bfloat16*)(smem + OFF_BHI + ((size_t)n * BSTR + k) * 2) = hi;
        *(__nv_bfloat16*)(smem + OFF_BLO + ((size_t)n * BSTR + k) * 2) = lo;
    }
    for (int k = tid; k < HID; k += NTHR) {          // FC row n = 32
        float x = W_fc[(size_t)blk * HID + k];
        __nv_bfloat16 hi = __float2bfloat16(x);
        __nv_bfloat16 lo = __float2bfloat16(x - __bfloat162float(hi));
        *(__nv_bfloat16*)(smem + OFF_BHI + ((size_t)32 * BSTR + k) * 2) = hi;
        *(__nv_bfloat16*)(smem + OFF_BLO + ((size_t)32 * BSTR + k) * 2) = lo;
    }
    if (tid < 32) {
        int u = tid >> 2, g = tid & 3;
        bsum[tid] = b_ih[g * HID + blk * 8 + u] + b_hh[g * HID + blk * 8 + u];
    }
    const float bfc = b_fc[blk];

    // Step-0 input gates: Xg[n][b] = z[b,:] . w_ih[row(n),:]
    for (int d = tid; d < 32 * BATCH; d += NTHR) {
        int n = d >> 7, b = d & 127;
        int u = n >> 2, g = n & 3;
        const float* wi = w_ih + (size_t)(g * HID + blk * 8 + u) * LAT;
        const float* zb = z + (size_t)b * LAT;
        float s = 0.f;
        #pragma unroll 4
        for (int l = 0; l < LAT; ++l) s += zb[l] * wi[l];
        Xg[n * BATCH + b] = s;
    }
    __syncthreads();

    // per-warp staging base + ldmatrix lane offsets
    const uint32_t wbase = sbase + OFF_A + (uint32_t)wid * A_WREG;
    const uint32_t aoff  = (uint32_t)((lane & 15) * (ASTR * 2) + (lane >> 4) * 16);
    const uint32_t bofft = (uint32_t)((lane & 7) * (BSTR * 2) + ((lane >> 3) & 1) * 16);
    // this lane's two cp.async slots per component: s = lane, lane+32
    const int s0r = lane >> 2, s0s = lane & 3;            // slot 0: row, seg
    const int s1r = (lane + 32) >> 2, s1s = lane & 3;     // slot 1

    // epilogue identity: pair (lane, lane^1); parity = lane&1 selects row r or r+8
    const int par = lane & 1;
    const int r_e = wid * 16 + (lane >> 2) + 8 * par;
    const int uo  = (lane >> 1) & 1;          // unit offset within n8 tile

    float cst[4] = {0.f, 0.f, 0.f, 0.f};      // c-state: units 2j+uo, row r_e

    for (int t = 0; t <= T_STEPS; ++t) {
        float d[5][4];
        #pragma unroll
        for (int j = 0; j < 5; ++j)
            #pragma unroll
            for (int q = 0; q < 4; ++q) d[j][q] = 0.f;

        if (t >= 1) {
            const __nv_bfloat16* hhi = g_hsp[t & 1][0];
            const __nv_bfloat16* hlo = g_hsp[t & 1][1];
            const size_t rb0 = (size_t)(wid * 16 + s0r) * HID;
            const size_t rb1 = (size_t)(wid * 16 + s1r) * HID;

            // warp-local prefetch of chunk m into stage m%3 (one group each)
            #define PREFETCH(m) do {                                          \
                uint32_t st = wbase + ((m) % 3) * A_WSTG;                     \
                size_t kb = (size_t)(m) * KCH;                                \
                cp_async16(st + s0r * 80 + s0s * 16,          hhi + rb0 + kb + s0s * 8); \
                cp_async16(st + s1r * 80 + s1s * 16,          hhi + rb1 + kb + s1s * 8); \
                cp_async16(st + A_COMP + s0r * 80 + s0s * 16, hlo + rb0 + kb + s0s * 8); \
                cp_async16(st + A_COMP + s1r * 80 + s1s * 16, hlo + rb1 + kb + s1s * 8); \
                cp_commit();                                                  \
            } while (0)

            PREFETCH(0);
            PREFETCH(1);

            for (int c = 0; c < NCHUNK; ++c) {
                if (c + 2 < NCHUNK) PREFETCH(c + 2);
                // wait until chunk c's group is complete (FIFO group order)
                if (c + 2 < NCHUNK)       cp_wait2();
                else if (c + 2 == NCHUNK) cp_wait1();
                else                      cp_wait0();
                __syncwarp();

                const uint32_t aHi = wbase + (c % 3) * A_WSTG + aoff;
                const uint32_t aLo = aHi + A_COMP;
                const uint32_t bB  = sbase + bofft + (uint32_t)c * (KCH * 2);

                #pragma unroll
                for (int kk = 0; kk < 2; ++kk) {
                    uint32_t ahi[4], alo[4];
                    ldsm4(ahi, aHi + kk * 32);
                    ldsm4(alo, aLo + kk * 32);
                    #pragma unroll
                    for (int j = 0; j < 5; ++j) {
                        uint32_t bhi[2], blo[2];
                        uint32_t brow = bB + (uint32_t)(j * 8) * (BSTR * 2) + kk * 32;
                        ldsm2(bhi, brow + OFF_BHI);
                        ldsm2(blo, brow + OFF_BLO);
                        mma16816(d[j], ahi, bhi);
                        mma16816(d[j], ahi, blo);
                        mma16816(d[j], alo, bhi);
                    }
                }
            }
            #undef PREFETCH
        }

        // ---------- epilogue ----------
        // y (D col 32, tile 4): lane&3==0 holds row r (d[4][0]); its partner
        // (lane&3==1) receives row r+8 via shfl of d[4][2].
        if (t >= 1) {
            float ysh = __shfl_xor_sync(0xffffffffu, d[4][2], 1);
            int l3 = lane & 3;
            if (l3 == 0)
                out[(size_t)r_e * (T_STEPS * PIECE) + (size_t)(t - 1) * PIECE + blk]
                    = d[4][0] + bfc;
            else if (l3 == 1)
                out[(size_t)r_e * (T_STEPS * PIECE) + (size_t)(t - 1) * PIECE + blk]
                    = ysh + bfc;
        }

        if (t < T_STEPS) {
            __nv_bfloat16 hh[4], hl[4];
            #pragma unroll
            for (int j = 0; j < 4; ++j) {
                int u = 2 * j + uo;
                float gv[4];
                if (t == 0) {
                    #pragma unroll
                    for (int g = 0; g < 4; ++g)
                        gv[g] = Xg[(u * 4 + g) * BATCH + r_e] + bsum[u * 4 + g];
                } else {
                    float x0 = __shfl_xor_sync(0xffffffffu, d[j][0], 1);
                    float x1 = __shfl_xor_sync(0xffffffffu, d[j][1], 1);
                    float x2 = __shfl_xor_sync(0xffffffffu, d[j][2], 1);
                    float x3 = __shfl_xor_sync(0xffffffffu, d[j][3], 1);
                    if (par == 0) {         // row r: own = gates 0,1 ; partner = 2,3
                        gv[0] = d[j][0]; gv[1] = d[j][1]; gv[2] = x0; gv[3] = x1;
                    } else {                // row r+8: partner = gates 0,1 ; own = 2,3
                        gv[0] = x2; gv[1] = x3; gv[2] = d[j][2]; gv[3] = d[j][3];
                    }
                    #pragma unroll
                    for (int g = 0; g < 4; ++g) gv[g] += bsum[u * 4 + g];
                }
                float i_ = sigf(gv[0]), f_ = sigf(gv[1]);
                float g_ = tanhf(gv[2]), o_ = sigf(gv[3]);
                float cc = f_ * cst[j] + i_ * g_;
                cst[j] = cc;
                float hv = o_ * tanhf(cc);
                __nv_bfloat16 hi = __float2bfloat16(hv);
                hh[j] = hi;
                hl[j] = __float2bfloat16(hv - __bfloat162float(hi));
            }
            // store h_t split: k = blk*8 + 2j + uo, row r_e
            __nv_bfloat16* dh = g_hsp[(t + 1) & 1][0] + (size_t)r_e * HID + blk * 8 + uo;
            __nv_bfloat16* dl = g_hsp[(t + 1) & 1][1] + (size_t)r_e * HID + blk * 8 + uo;
            #pragma unroll
            for (int j = 0; j < 4; ++j) { dh[2 * j] = hh[j]; dl[2 * j] = hl[j]; }

            grid_bar();     // h_t visible to all CTAs before step t+1
        }
    }
}

// ---------------- launch ----------------
extern "C" void kernel_launch(void* const* d_in, const int* in_sizes, int n_in,
                              void* d_out, int out_size)
{
    // metadata order: current_batch_size, z, w_ih, w_hh, b_ih, b_hh, W_fc, b_fc
    int off = (n_in >= 8) ? 1 : 0;
    const float* z    = (const float*)d_in[off + 0];
    const float* w_ih = (const float*)d_in[off + 1];
    const float* w_hh = (const float*)d_in[off + 2];
    const float* b_ih = (const float*)d_in[off + 3];
    const float* b_hh = (const float*)d_in[off + 4];
    const float* W_fc = (const float*)d_in[off + 5];
    const float* b_fc = (const float*)d_in[off + 6];

    cudaFuncSetAttribute(lstm_mma_kernel,
                         cudaFuncAttributeMaxDynamicSharedMemorySize, SMEM_BYTES);

    lstm_mma_kernel<<<NBLK, NTHR, SMEM_BYTES>>>(
        z, w_ih, w_hh, b_ih, b_hh, W_fc, b_fc, (float*)d_out);
}